// round 14
// baseline (speedup 1.0000x reference)
#include <cuda_runtime.h>
#include <cuda_bf16.h>
#include <cuda_fp16.h>

#define NNODE 100000
#define EMAX  1600000
#define CDIM 64

__device__ __align__(16) float  g_h[NNODE * CDIM];
__device__ __align__(16) float  g_agg[NNODE * CDIM];
__device__ __align__(16) __half g_PAh[NNODE * CDIM];   // fp16: h·WA + pos·Wp
__device__ __align__(16) __half g_PBh[NNODE * CDIM];   // fp16: h·WB + b0 − pos·Wp
__device__ __align__(8)  int2   g_sd[EMAX];            // BYTE offsets into half arrays: (s*128, d*128)
__device__ __align__(16) float  g_W0c[2][8192];        // kpair-packed combined [W0h; eW1·W0a]
__device__ float g_v[2][64];                           // eb1·W0a
__device__ int   g_deg[NNODE];
__device__ int   g_mode;                               // 1 = int64 indices, 0 = int32

__device__ __forceinline__ float elu_f(float v) {
    return v > 0.f ? v : expm1f(v);
}
__device__ __forceinline__ float elu_fast(float v) {
    float e = __expf(v) - 1.f;
    return v > 0.f ? v : e;
}

// packed fp32x2 helpers (sm_100+)
__device__ __forceinline__ void ffma2(unsigned long long& d, unsigned long long a, unsigned long long b) {
    asm("fma.rn.f32x2 %0, %1, %2, %0;" : "+l"(d) : "l"(a), "l"(b));
}
__device__ __forceinline__ float usum(unsigned long long v) {
    float lo, hi;
    asm("mov.b64 {%0,%1}, %2;" : "=f"(lo), "=f"(hi) : "l"(v));
    return lo + hi;
}
__device__ __forceinline__ void red_add_v4(float* addr, float x, float y, float z, float w) {
    asm volatile("red.global.add.v4.f32 [%0], {%1, %2, %3, %4};"
                 :: "l"(addr), "f"(x), "f"(y), "f"(z), "f"(w) : "memory");
}

// ------------------------------------------------------------------ launch 0: probe dtype + zero deg
__global__ void probe_zero_kernel(const int* __restrict__ w, int Nn) {
    if (blockIdx.x == 0 && threadIdx.x == 0) {
        bool all_odd_zero = true;
        for (int i = 1; i < 64; i += 2)
            if (w[i] != 0) { all_odd_zero = false; break; }
        g_mode = all_odd_zero ? 1 : 0;
    }
    for (int i = blockIdx.x * blockDim.x + threadIdx.x; i < Nn; i += gridDim.x * blockDim.x)
        g_deg[i] = 0;
}

// ------------------------------------------------------------------ launch 1: convert indices + deg + zero agg (layer 0)
__global__ void convert_kernel(const int* __restrict__ w, int Ecnt, int Nn) {
    int mode = g_mode;
    for (int e = blockIdx.x * blockDim.x + threadIdx.x; e < Ecnt; e += gridDim.x * blockDim.x) {
        int s, d;
        if (mode) { s = w[2 * e]; d = w[2 * (Ecnt + e)]; }
        else      { s = w[e];     d = w[Ecnt + e]; }
        s = min(max(s, 0), NNODE - 1);
        d = min(max(d, 0), NNODE - 1);
        atomicAdd(&g_deg[d], 1);
        g_sd[e] = make_int2(s * 128, d * 128);
    }
    float4* p = reinterpret_cast<float4*>(g_agg);
    int n4 = Nn * 16;
    for (int i = blockIdx.x * blockDim.x + threadIdx.x; i < n4; i += gridDim.x * blockDim.x)
        p[i] = make_float4(0.f, 0.f, 0.f, 0.f);
}

// ------------------------------------------------------------------ launch 2: encoder + precompute(layer 0) fused (batch 4)
__global__ void enc_pre_kernel(const float* __restrict__ x, const float* __restrict__ pos,
                               const float* __restrict__ W0e, const float* __restrict__ b0e,
                               const float* __restrict__ W1e, const float* __restrict__ b1e,
                               const float* __restrict__ E0, const float* __restrict__ eb0,
                               int Nn) {
    extern __shared__ float sm[];
    float* sW1 = sm;             // 4096 kpair-packed (enc W1)
    float* sWA = sm + 4096;      // 4096
    float* sWB = sm + 8192;      // 4096
    float* sW0 = sm + 12288;     // 192 (enc W0)
    float* sWp = sm + 12480;     // 192
    float* sbe0 = sm + 12672;    // 64
    float* sbe1 = sm + 12736;    // 64
    float* sb0  = sm + 12800;    // 64 (edge b0)
    float* stage = sm + 12864;   // 8 warps * 320

    for (int t = threadIdx.x; t < 4096; t += blockDim.x) {
        int c = t & 3, lane_ = (t >> 2) & 31, kp = t >> 7;
        int k = 2 * kp + (c & 1);
        int col = lane_ + ((c & 2) ? 32 : 0);
        sW1[t] = W1e[k * 64 + col];
        float wC = E0[(128 + k) * 64 + col];
        sWA[t] = E0[k * 64 + col] + wC;
        sWB[t] = E0[(64 + k) * 64 + col] - wC;
    }
    for (int t = threadIdx.x; t < 192; t += blockDim.x) {
        sW0[t] = W0e[t];
        sWp[t] = E0[(192 + (t >> 6)) * 64 + (t & 63)];
    }
    if (threadIdx.x < 64) {
        sbe0[threadIdx.x] = b0e[threadIdx.x];
        sbe1[threadIdx.x] = b1e[threadIdx.x];
        sb0[threadIdx.x]  = eb0[threadIdx.x];
    }
    __syncthreads();

    int lane = threadIdx.x & 31;
    int wid  = threadIdx.x >> 5;
    float* wbase = stage + wid * 320;
    const ulonglong2* W1v = reinterpret_cast<const ulonglong2*>(sW1);
    const ulonglong2* WAv = reinterpret_cast<const ulonglong2*>(sWA);
    const ulonglong2* WBv = reinterpret_cast<const ulonglong2*>(sWB);
    const unsigned long long* nU = reinterpret_cast<const unsigned long long*>(wbase);
    float* hF = wbase;

    int rL = ((lane >> 1) * 5) * 2 + (lane & 1);
    int rH = ((16 + (lane >> 1)) * 5) * 2 + (lane & 1);

    int wg = blockIdx.x * (blockDim.x >> 5) + wid;
    int ws = gridDim.x * (blockDim.x >> 5);
    for (int base = wg * 4; base < Nn; base += ws * 4) {
        float p0v[4], p1v[4], p2v[4];
#pragma unroll
        for (int i = 0; i < 4; i++) {
            int n = base + i;
            float h0 = 0.f, h1 = 0.f;
            if (n < Nn) {
                float x0 = __ldg(&x[n * 3 + 0]), x1 = __ldg(&x[n * 3 + 1]), x2 = __ldg(&x[n * 3 + 2]);
                h0 = elu_f(x0 * sW0[lane]      + x1 * sW0[64 + lane]      + x2 * sW0[128 + lane]      + sbe0[lane]);
                h1 = elu_f(x0 * sW0[lane + 32] + x1 * sW0[64 + lane + 32] + x2 * sW0[128 + lane + 32] + sbe0[lane + 32]);
                p0v[i] = __ldg(&pos[n * 3 + 0]);
                p1v[i] = __ldg(&pos[n * 3 + 1]);
                p2v[i] = __ldg(&pos[n * 3 + 2]);
            } else { p0v[i] = p1v[i] = p2v[i] = 0.f; }
            hF[rL + 2 * i] = h0;
            hF[rH + 2 * i] = h1;
        }
        __syncwarp();

        unsigned long long a0[4] = {0,0,0,0}, a1[4] = {0,0,0,0};
#pragma unroll 4
        for (int kp = 0; kp < 32; kp++) {
            ulonglong2 w = W1v[kp * 32 + lane];
#pragma unroll
            for (int i = 0; i < 4; i++) {
                unsigned long long v = nU[kp * 5 + i];
                ffma2(a0[i], v, w.x); ffma2(a1[i], v, w.y);
            }
        }
        float b1a = sbe1[lane], b1b = sbe1[lane + 32];
        float hL[4], hH[4];
#pragma unroll
        for (int i = 0; i < 4; i++) {
            hL[i] = usum(a0[i]) + b1a;
            hH[i] = usum(a1[i]) + b1b;
            int n = base + i;
            if (n < Nn) {
                g_h[n * 64 + lane]      = hL[i];
                g_h[n * 64 + 32 + lane] = hH[i];
            }
        }
        __syncwarp();
#pragma unroll
        for (int i = 0; i < 4; i++) {
            hF[rL + 2 * i] = hL[i];
            hF[rH + 2 * i] = hH[i];
        }
        __syncwarp();

        unsigned long long aA0[4] = {0,0,0,0}, aA1[4] = {0,0,0,0};
        unsigned long long aB0[4] = {0,0,0,0}, aB1[4] = {0,0,0,0};
#pragma unroll 4
        for (int kp = 0; kp < 32; kp++) {
            ulonglong2 wa = WAv[kp * 32 + lane];
            ulonglong2 wb = WBv[kp * 32 + lane];
#pragma unroll
            for (int i = 0; i < 4; i++) {
                unsigned long long v = nU[kp * 5 + i];
                ffma2(aA0[i], v, wa.x); ffma2(aA1[i], v, wa.y);
                ffma2(aB0[i], v, wb.x); ffma2(aB1[i], v, wb.y);
            }
        }
        float b0a = sb0[lane], b0b = sb0[lane + 32];
        float wpL0 = sWp[lane], wpL1 = sWp[64 + lane], wpL2 = sWp[128 + lane];
        float wpH0 = sWp[lane + 32], wpH1 = sWp[64 + lane + 32], wpH2 = sWp[128 + lane + 32];
#pragma unroll
        for (int i = 0; i < 4; i++) {
            int n = base + i;
            if (n < Nn) {
                float wpa = p0v[i] * wpL0 + p1v[i] * wpL1 + p2v[i] * wpL2;
                float wpb = p0v[i] * wpH0 + p1v[i] * wpH1 + p2v[i] * wpH2;
                g_PAh[n * 64 + lane]      = __float2half(usum(aA0[i]) + wpa);
                g_PAh[n * 64 + 32 + lane] = __float2half(usum(aA1[i]) + wpb);
                g_PBh[n * 64 + lane]      = __float2half(usum(aB0[i]) + b0a - wpa);
                g_PBh[n * 64 + 32 + lane] = __float2half(usum(aB1[i]) + b0b - wpb);
            }
        }
        __syncwarp();
    }
}

// ------------------------------------------------------------------ launch 3 (PROFILED): edge scatter (fp16 gathers) — round-12 proven
__global__ void edge_scatter_kernel(int Ecnt) {
    int lane = threadIdx.x & 31;
    int wid  = threadIdx.x >> 5;
    int slot = lane >> 4;
    int ch8  = (lane & 15) * 8;

    const char* PAc = reinterpret_cast<const char*>(g_PAh) + ch8;
    const char* PBc = reinterpret_cast<const char*>(g_PBh) + ch8;
    char*       AGc = reinterpret_cast<char*>(g_agg) + ch8 * 2;

    int wg = blockIdx.x * (blockDim.x >> 5) + wid;
    int ws = gridDim.x * (blockDim.x >> 5);
    for (int base = wg * 8; base < Ecnt; base += ws * 8) {
        int2 ed[4];
        uint2 pa[4], pb[4];
#pragma unroll
        for (int p = 0; p < 4; p++) {
            int e = base + p * 2 + slot;
            ed[p] = (e < Ecnt) ? __ldg(&g_sd[e]) : make_int2(-1, -1);
        }
#pragma unroll
        for (int p = 0; p < 4; p++) {
            if (ed[p].x >= 0) {
                pa[p] = *reinterpret_cast<const uint2*>(PAc + ed[p].x);
                pb[p] = *reinterpret_cast<const uint2*>(PBc + ed[p].y);
            }
        }
#pragma unroll
        for (int p = 0; p < 4; p++) {
            if (ed[p].x >= 0) {
                float2 a0 = __half22float2(*reinterpret_cast<__half2*>(&pa[p].x));
                float2 a1 = __half22float2(*reinterpret_cast<__half2*>(&pa[p].y));
                float2 b0 = __half22float2(*reinterpret_cast<__half2*>(&pb[p].x));
                float2 b1 = __half22float2(*reinterpret_cast<__half2*>(&pb[p].y));
                float hx = elu_fast(a0.x + b0.x);
                float hy = elu_fast(a0.y + b0.y);
                float hz = elu_fast(a1.x + b1.x);
                float hw = elu_fast(a1.y + b1.y);
                red_add_v4(reinterpret_cast<float*>(AGc + ((size_t)ed[p].y << 1)), hx, hy, hz, hw);
            }
        }
    }
}

// ------------------------------------------------------------------ prep: fold eW1/eb1 into node W0 (both layers)
__global__ void prep_kernel(const float* __restrict__ eW1, const float* __restrict__ eb1,
                            const float* __restrict__ nW0) {
    int l = blockIdx.x;
    const float* E1 = eW1 + (size_t)l * 4096;
    const float* B1 = eb1 + (size_t)l * 64;
    const float* W0 = nW0 + (size_t)l * 8192;
    __shared__ float sE1[4096];
    __shared__ float sW0a[4096];
    __shared__ float sB1[64];
    for (int t = threadIdx.x; t < 4096; t += blockDim.x) {
        sE1[t]  = E1[t];
        sW0a[t] = W0[4096 + t];
    }
    if (threadIdx.x < 64) sB1[threadIdx.x] = B1[threadIdx.x];
    __syncthreads();

    if (threadIdx.x < 64) {
        float acc = 0.f;
        for (int m = 0; m < 64; m++) acc += sB1[m] * sW0a[m * 64 + threadIdx.x];
        g_v[l][threadIdx.x] = acc;
    }
    for (int t = threadIdx.x; t < 8192; t += blockDim.x) {
        int c = t & 3, lane_ = (t >> 2) & 31, kp = t >> 7;
        int k = 2 * kp + (c & 1);
        int col = lane_ + ((c & 2) ? 32 : 0);
        float val;
        if (k < 64) {
            val = W0[k * 64 + col];
        } else {
            int kk = k - 64;
            float acc = 0.f;
            for (int m = 0; m < 64; m++) acc += sE1[kk * 64 + m] * sW0a[m * 64 + col];
            val = acc;
        }
        g_W0c[l][t] = val;
    }
}

// ------------------------------------------------------------------ node_pre: node update (l0) + precompute(l1) + zero agg  (BATCH 8)
__global__ void node_pre_kernel(const float* __restrict__ W0c, const float* __restrict__ vv,
                                const float* __restrict__ W1, const float* __restrict__ b0,
                                const float* __restrict__ b1,
                                const float* __restrict__ E0, const float* __restrict__ eb0_1,
                                const float* __restrict__ pos, int Nn) {
    extern __shared__ float sm[];
    float* sW0 = sm;              // 8192
    float* sW1 = sm + 8192;       // 4096
    float* sWA = sm + 12288;      // 4096 (layer 1)
    float* sWB = sm + 16384;      // 4096
    float* sWp = sm + 20480;      // 192
    float* sv  = sm + 20672;      // 64
    float* snb0 = sm + 20736;     // 64
    float* snb1 = sm + 20800;     // 64
    float* seb0 = sm + 20864;     // 64
    float* stage = sm + 20928;    // 8 warps * 1152 floats (64 kpairs * 9 u64)

    for (int t = threadIdx.x; t < 8192; t += blockDim.x) sW0[t] = W0c[t];
    for (int t = threadIdx.x; t < 4096; t += blockDim.x) {
        int c = t & 3, lane_ = (t >> 2) & 31, kp = t >> 7;
        int k = 2 * kp + (c & 1);
        int col = lane_ + ((c & 2) ? 32 : 0);
        sW1[t] = W1[k * 64 + col];
        float wC = E0[(128 + k) * 64 + col];
        sWA[t] = E0[k * 64 + col] + wC;
        sWB[t] = E0[(64 + k) * 64 + col] - wC;
    }
    for (int t = threadIdx.x; t < 192; t += blockDim.x)
        sWp[t] = E0[(192 + (t >> 6)) * 64 + (t & 63)];
    if (threadIdx.x < 64) {
        sv[threadIdx.x]   = vv[threadIdx.x];
        snb0[threadIdx.x] = b0[threadIdx.x];
        snb1[threadIdx.x] = b1[threadIdx.x];
        seb0[threadIdx.x] = eb0_1[threadIdx.x];
    }
    __syncthreads();

    int lane = threadIdx.x & 31;
    int wid  = threadIdx.x >> 5;
    float* wbase = stage + wid * 1152;
    float2* nP = reinterpret_cast<float2*>(wbase);   // u64-indexed, stride 9 per kpair
    const ulonglong2* W0v = reinterpret_cast<const ulonglong2*>(sW0);
    const ulonglong2* W1v = reinterpret_cast<const ulonglong2*>(sW1);
    const ulonglong2* WAv = reinterpret_cast<const ulonglong2*>(sWA);
    const ulonglong2* WBv = reinterpret_cast<const ulonglong2*>(sWB);
    const unsigned long long* nU = reinterpret_cast<const unsigned long long*>(nP);
    float* hF = wbase;

    int rL = ((lane >> 1) * 9) * 2 + (lane & 1);
    int rH = ((16 + (lane >> 1)) * 9) * 2 + (lane & 1);
    float wpL0 = sWp[lane], wpL1 = sWp[64 + lane], wpL2 = sWp[128 + lane];
    float wpH0 = sWp[lane + 32], wpH1 = sWp[64 + lane + 32], wpH2 = sWp[128 + lane + 32];

    int wg = blockIdx.x * (blockDim.x >> 5) + wid;
    int ws = gridDim.x * (blockDim.x >> 5);
    for (int base = wg * 8; base < Nn; base += ws * 8) {
        float degf[8], wpa[8], wpb[8];
#pragma unroll
        for (int i = 0; i < 8; i++) {
            int n = base + i;
            if (n < Nn) {
                nP[lane * 9 + i]        = reinterpret_cast<const float2*>(g_h + n * 64)[lane];
                nP[(32 + lane) * 9 + i] = reinterpret_cast<const float2*>(g_agg + n * 64)[lane];
                degf[i] = (float)__ldg(&g_deg[n]);
                float q0 = __ldg(&pos[n * 3 + 0]);
                float q1 = __ldg(&pos[n * 3 + 1]);
                float q2 = __ldg(&pos[n * 3 + 2]);
                wpa[i] = q0 * wpL0 + q1 * wpL1 + q2 * wpL2;
                wpb[i] = q0 * wpH0 + q1 * wpH1 + q2 * wpH2;
                reinterpret_cast<float2*>(g_agg + n * 64)[lane] = make_float2(0.f, 0.f);
            } else {
                nP[lane * 9 + i]        = make_float2(0.f, 0.f);
                nP[(32 + lane) * 9 + i] = make_float2(0.f, 0.f);
                degf[i] = 0.f; wpa[i] = 0.f; wpb[i] = 0.f;
            }
        }
        __syncwarp();

        // hidden = elu([h, Hsum]·W0c + deg·v + b0)
        unsigned long long c0[8] = {0,0,0,0,0,0,0,0}, c1[8] = {0,0,0,0,0,0,0,0};
#pragma unroll 4
        for (int kp = 0; kp < 64; kp++) {
            ulonglong2 w = W0v[kp * 32 + lane];
#pragma unroll
            for (int i = 0; i < 8; i++) {
                unsigned long long v = nU[kp * 9 + i];
                ffma2(c0[i], v, w.x); ffma2(c1[i], v, w.y);
            }
        }
        {
            float b0a = snb0[lane], b0b = snb0[lane + 32];
            float svL = sv[lane],   svH = sv[lane + 32];
            float hL[8], hH[8];
#pragma unroll
            for (int i = 0; i < 8; i++) {
                hL[i] = elu_f(usum(c0[i]) + degf[i] * svL + b0a);
                hH[i] = elu_f(usum(c1[i]) + degf[i] * svH + b0b);
            }
            __syncwarp();
#pragma unroll
            for (int i = 0; i < 8; i++) {
                hF[rL + 2 * i] = hL[i];
                hF[rH + 2 * i] = hH[i];
            }
        }
        __syncwarp();

        // u = hidden·W1 + b1 ; newh = oldh + u → g_h and restage
#pragma unroll
        for (int i = 0; i < 8; i++) { c0[i] = 0ull; c1[i] = 0ull; }
#pragma unroll 4
        for (int kp = 0; kp < 32; kp++) {
            ulonglong2 w = W1v[kp * 32 + lane];
#pragma unroll
            for (int i = 0; i < 8; i++) {
                unsigned long long v = nU[kp * 9 + i];
                ffma2(c0[i], v, w.x); ffma2(c1[i], v, w.y);
            }
        }
        {
            float b1a = snb1[lane], b1b = snb1[lane + 32];
            float nhL[8], nhH[8];
#pragma unroll
            for (int i = 0; i < 8; i++) {
                int n = base + i;
                if (n < Nn) {
                    nhL[i] = g_h[n * 64 + lane]      + usum(c0[i]) + b1a;
                    nhH[i] = g_h[n * 64 + 32 + lane] + usum(c1[i]) + b1b;
                    g_h[n * 64 + lane]      = nhL[i];
                    g_h[n * 64 + 32 + lane] = nhH[i];
                } else { nhL[i] = 0.f; nhH[i] = 0.f; }
            }
            __syncwarp();
#pragma unroll
            for (int i = 0; i < 8; i++) {
                hF[rL + 2 * i] = nhL[i];
                hF[rH + 2 * i] = nhH[i];
            }
        }
        __syncwarp();

        // PA pass (layer 1)
#pragma unroll
        for (int i = 0; i < 8; i++) { c0[i] = 0ull; c1[i] = 0ull; }
#pragma unroll 4
        for (int kp = 0; kp < 32; kp++) {
            ulonglong2 wa = WAv[kp * 32 + lane];
#pragma unroll
            for (int i = 0; i < 8; i++) {
                unsigned long long v = nU[kp * 9 + i];
                ffma2(c0[i], v, wa.x); ffma2(c1[i], v, wa.y);
            }
        }
#pragma unroll
        for (int i = 0; i < 8; i++) {
            int n = base + i;
            if (n < Nn) {
                g_PAh[n * 64 + lane]      = __float2half(usum(c0[i]) + wpa[i]);
                g_PAh[n * 64 + 32 + lane] = __float2half(usum(c1[i]) + wpb[i]);
            }
        }

        // PB pass (layer 1)
#pragma unroll
        for (int i = 0; i < 8; i++) { c0[i] = 0ull; c1[i] = 0ull; }
#pragma unroll 4
        for (int kp = 0; kp < 32; kp++) {
            ulonglong2 wb = WBv[kp * 32 + lane];
#pragma unroll
            for (int i = 0; i < 8; i++) {
                unsigned long long v = nU[kp * 9 + i];
                ffma2(c0[i], v, wb.x); ffma2(c1[i], v, wb.y);
            }
        }
        {
            float eb0a = seb0[lane], eb0b = seb0[lane + 32];
#pragma unroll
            for (int i = 0; i < 8; i++) {
                int n = base + i;
                if (n < Nn) {
                    g_PBh[n * 64 + lane]      = __float2half(usum(c0[i]) + eb0a - wpa[i]);
                    g_PBh[n * 64 + 32 + lane] = __float2half(usum(c1[i]) + eb0b - wpb[i]);
                }
            }
        }
        __syncwarp();
    }
}

// ------------------------------------------------------------------ node_dec: node update (l1) + decoder  (BATCH 8)
__global__ void node_dec_kernel(const float* __restrict__ W0c, const float* __restrict__ vv,
                                const float* __restrict__ W1, const float* __restrict__ b0,
                                const float* __restrict__ b1,
                                const float* __restrict__ dW0, const float* __restrict__ db0,
                                const float* __restrict__ dW1, const float* __restrict__ db1,
                                float* __restrict__ out, int Nn) {
    extern __shared__ float sm[];
    float* sW0 = sm;              // 8192
    float* sW1 = sm + 8192;       // 4096
    float* sdW0 = sm + 12288;     // 4096
    float* sdW1 = sm + 16384;     // 192
    float* sv  = sm + 16576;      // 64
    float* snb0 = sm + 16640;     // 64
    float* snb1 = sm + 16704;     // 64
    float* sdb0 = sm + 16768;     // 64
    float* sdb1 = sm + 16832;     // 4
    float* stage = sm + 16836;    // 8 warps * 1152

    for (int t = threadIdx.x; t < 8192; t += blockDim.x) sW0[t] = W0c[t];
    for (int t = threadIdx.x; t < 4096; t += blockDim.x) {
        int c = t & 3, lane_ = (t >> 2) & 31, kp = t >> 7;
        int k = 2 * kp + (c & 1);
        int col = lane_ + ((c & 2) ? 32 : 0);
        sW1[t] = W1[k * 64 + col];
        sdW0[t] = dW0[k * 64 + col];
    }
    for (int t = threadIdx.x; t < 192; t += blockDim.x) sdW1[t] = dW1[t];
    if (threadIdx.x < 64) {
        sv[threadIdx.x]   = vv[threadIdx.x];
        snb0[threadIdx.x] = b0[threadIdx.x];
        snb1[threadIdx.x] = b1[threadIdx.x];
        sdb0[threadIdx.x] = db0[threadIdx.x];
    }
    if (threadIdx.x < 3) sdb1[threadIdx.x] = db1[threadIdx.x];
    __syncthreads();

    int lane = threadIdx.x & 31;
    int wid  = threadIdx.x >> 5;
    float* wbase = stage + wid * 1152;
    float2* nP = reinterpret_cast<float2*>(wbase);
    const ulonglong2* W0v = reinterpret_cast<const ulonglong2*>(sW0);
    const ulonglong2* W1v = reinterpret_cast<const ulonglong2*>(sW1);
    const ulonglong2* dW0v = reinterpret_cast<const ulonglong2*>(sdW0);
    const unsigned long long* nU = reinterpret_cast<const unsigned long long*>(nP);
    float* hF = wbase;

    int rL = ((lane >> 1) * 9) * 2 + (lane & 1);
    int rH = ((16 + (lane >> 1)) * 9) * 2 + (lane & 1);

    int wg = blockIdx.x * (blockDim.x >> 5) + wid;
    int ws = gridDim.x * (blockDim.x >> 5);
    for (int base = wg * 8; base < Nn; base += ws * 8) {
        float degf[8];
#pragma unroll
        for (int i = 0; i < 8; i++) {
            int n = base + i;
            if (n < Nn) {
                nP[lane * 9 + i]        = reinterpret_cast<const float2*>(g_h + n * 64)[lane];
                nP[(32 + lane) * 9 + i] = reinterpret_cast<const float2*>(g_agg + n * 64)[lane];
                degf[i] = (float)__ldg(&g_deg[n]);
            } else {
                nP[lane * 9 + i]        = make_float2(0.f, 0.f);
                nP[(32 + lane) * 9 + i] = make_float2(0.f, 0.f);
                degf[i] = 0.f;
            }
        }
        __syncwarp();

        // hidden = elu([h, Hsum]·W0c + deg·v + b0)
        unsigned long long c0[8] = {0,0,0,0,0,0,0,0}, c1[8] = {0,0,0,0,0,0,0,0};
#pragma unroll 4
        for (int kp = 0; kp < 64; kp++) {
            ulonglong2 w = W0v[kp * 32 + lane];
#pragma unroll
            for (int i = 0; i < 8; i++) {
                unsigned long long v = nU[kp * 9 + i];
                ffma2(c0[i], v, w.x); ffma2(c1[i], v, w.y);
            }
        }
        {
            float b0a = snb0[lane], b0b = snb0[lane + 32];
            float svL = sv[lane],   svH = sv[lane + 32];
            float hL[8], hH[8];
#pragma unroll
            for (int i = 0; i < 8; i++) {
                hL[i] = elu_f(usum(c0[i]) + degf[i] * svL + b0a);
                hH[i] = elu_f(usum(c1[i]) + degf[i] * svH + b0b);
            }
            __syncwarp();
#pragma unroll
            for (int i = 0; i < 8; i++) {
                hF[rL + 2 * i] = hL[i];
                hF[rH + 2 * i] = hH[i];
            }
        }
        __syncwarp();

        // u = hidden·W1 + b1 ; newh = oldh + u (registers → restage)
#pragma unroll
        for (int i = 0; i < 8; i++) { c0[i] = 0ull; c1[i] = 0ull; }
#pragma unroll 4
        for (int kp = 0; kp < 32; kp++) {
            ulonglong2 w = W1v[kp * 32 + lane];
#pragma unroll
            for (int i = 0; i < 8; i++) {
                unsigned long long v = nU[kp * 9 + i];
                ffma2(c0[i], v, w.x); ffma2(c1[i], v, w.y);
            }
        }
        {
            float b1a = snb1[lane], b1b = snb1[lane + 32];
            float nhL[8], nhH[8];
#pragma unroll
            for (int i = 0; i < 8; i++) {
                int n = base + i;
                if (n < Nn) {
                    nhL[i] = g_h[n * 64 + lane]      + usum(c0[i]) + b1a;
                    nhH[i] = g_h[n * 64 + 32 + lane] + usum(c1[i]) + b1b;
                } else { nhL[i] = 0.f; nhH[i] = 0.f; }
            }
            __syncwarp();
#pragma unroll
            for (int i = 0; i < 8; i++) {
                hF[rL + 2 * i] = nhL[i];
                hF[rH + 2 * i] = nhH[i];
            }
        }
        __syncwarp();

        // decoder: hidden = elu(newh·dW0 + db0) ; out = hidden·dW1 + db1
#pragma unroll
        for (int i = 0; i < 8; i++) { c0[i] = 0ull; c1[i] = 0ull; }
#pragma unroll 4
        for (int kp = 0; kp < 32; kp++) {
            ulonglong2 w = dW0v[kp * 32 + lane];
#pragma unroll
            for (int i = 0; i < 8; i++) {
                unsigned long long v = nU[kp * 9 + i];
                ffma2(c0[i], v, w.x); ffma2(c1[i], v, w.y);
            }
        }
        float db0a = sdb0[lane], db0b = sdb0[lane + 32];
        float w1L0 = sdW1[lane * 3 + 0], w1L1 = sdW1[lane * 3 + 1], w1L2 = sdW1[lane * 3 + 2];
        float w1H0 = sdW1[(lane + 32) * 3 + 0], w1H1 = sdW1[(lane + 32) * 3 + 1], w1H2 = sdW1[(lane + 32) * 3 + 2];
#pragma unroll
        for (int i = 0; i < 8; i++) {
            int n = base + i;
            float hid0 = elu_f(usum(c0[i]) + db0a);
            float hid1 = elu_f(usum(c1[i]) + db0b);
            float p0 = hid0 * w1L0 + hid1 * w1H0;
            float p1 = hid0 * w1L1 + hid1 * w1H1;
            float p2 = hid0 * w1L2 + hid1 * w1H2;
#pragma unroll
            for (int off = 16; off; off >>= 1) {
                p0 += __shfl_xor_sync(~0u, p0, off);
                p1 += __shfl_xor_sync(~0u, p1, off);
                p2 += __shfl_xor_sync(~0u, p2, off);
            }
            if (lane == 0 && n < Nn) {
                out[n * 3 + 0] = p0 + sdb1[0];
                out[n * 3 + 1] = p1 + sdb1[1];
                out[n * 3 + 2] = p2 + sdb1[2];
            }
        }
        __syncwarp();
    }
}

// ------------------------------------------------------------------ launch
extern "C" void kernel_launch(void* const* d_in, const int* in_sizes, int n_in,
                              void* d_out, int out_size) {
    const float* x      = (const float*)d_in[0];
    const float* pos    = (const float*)d_in[1];
    const int*   ei     = (const int*)d_in[2];
    const float* enc_W0 = (const float*)d_in[3];
    const float* enc_b0 = (const float*)d_in[4];
    const float* enc_W1 = (const float*)d_in[5];
    const float* enc_b1 = (const float*)d_in[6];
    const float* dec_W0 = (const float*)d_in[7];
    const float* dec_b0 = (const float*)d_in[8];
    const float* dec_W1 = (const float*)d_in[9];
    const float* dec_b1 = (const float*)d_in[10];
    const float* eW0    = (const float*)d_in[11];
    const float* eb0    = (const float*)d_in[12];
    const float* eW1    = (const float*)d_in[13];
    const float* eb1    = (const float*)d_in[14];
    const float* nW0    = (const float*)d_in[15];
    const float* nb0    = (const float*)d_in[16];
    const float* nW1    = (const float*)d_in[17];
    const float* nb1    = (const float*)d_in[18];

    int Nn   = in_sizes[0] / 3;
    int Ecnt = in_sizes[2] / 2;
    if (Ecnt > EMAX) Ecnt = EMAX;
    float* out = (float*)d_out;

    const int ENCP_SMEM = (12864 + 8 * 320) * 4;    // 61,696 B
    const int NPRE_SMEM = (20928 + 8 * 1152) * 4;   // 120,576 B
    const int NDEC_SMEM = (16836 + 8 * 1152) * 4;   // 104,208 B
    cudaFuncSetAttribute(enc_pre_kernel,  cudaFuncAttributeMaxDynamicSharedMemorySize, ENCP_SMEM);
    cudaFuncSetAttribute(node_pre_kernel, cudaFuncAttributeMaxDynamicSharedMemorySize, NPRE_SMEM);
    cudaFuncSetAttribute(node_dec_kernel, cudaFuncAttributeMaxDynamicSharedMemorySize, NDEC_SMEM);

    const int TPB = 256;
    const float* E0_0 = eW0;
    const float* E0_1 = eW0 + (size_t)195 * 64;

    float* w0c; float* vv;
    cudaGetSymbolAddress((void**)&w0c, g_W0c);
    cudaGetSymbolAddress((void**)&vv,  g_v);

    probe_zero_kernel<<<148, TPB>>>(ei, Nn);                                          // 0
    convert_kernel<<<444, TPB>>>(ei, Ecnt, Nn);                                       // 1
    enc_pre_kernel<<<296, TPB, ENCP_SMEM>>>(x, pos, enc_W0, enc_b0, enc_W1, enc_b1,
                                            E0_0, eb0, Nn);                           // 2
    edge_scatter_kernel<<<888, TPB>>>(Ecnt);                                          // 3  ← profiled
    prep_kernel<<<2, 256>>>(eW1, eb1, nW0);                                           // 4
    node_pre_kernel<<<148, TPB, NPRE_SMEM>>>(w0c, vv, nW1, nb0, nb1,
                                             E0_1, eb0 + 64, pos, Nn);                // 5
    edge_scatter_kernel<<<888, TPB>>>(Ecnt);                                          // 6
    node_dec_kernel<<<148, TPB, NDEC_SMEM>>>(w0c + 8192, vv + 64,
                                             nW1 + (size_t)64 * 64, nb0 + 64, nb1 + 64,
                                             dec_W0, dec_b0, dec_W1, dec_b1, out, Nn); // 7
}

// round 15
// speedup vs baseline: 1.0990x; 1.0990x over previous
#include <cuda_runtime.h>
#include <cuda_bf16.h>
#include <cuda_fp16.h>

#define NNODE 100000
#define EMAX  1600000
#define CDIM 64

__device__ __align__(16) float  g_h[NNODE * CDIM];
__device__ __align__(16) float  g_agg[NNODE * CDIM];
__device__ __align__(16) __half g_PAh[NNODE * CDIM];   // fp16: h·WA + pos·Wp
__device__ __align__(16) __half g_PBh[NNODE * CDIM];   // fp16: h·WB + b0 − pos·Wp
__device__ __align__(8)  int2   g_sd[EMAX];            // BYTE offsets into half arrays: (s*128, d*128)
__device__ __align__(16) float  g_W0c[2][8192];        // kpair-packed combined [W0h; eW1·W0a]
__device__ float g_v[2][64];                           // eb1·W0a
__device__ int   g_deg[NNODE];
__device__ int   g_mode;                               // 1 = int64 indices, 0 = int32

__device__ __forceinline__ float elu_f(float v) {
    return v > 0.f ? v : expm1f(v);
}
__device__ __forceinline__ float elu_fast(float v) {
    float e = __expf(v) - 1.f;
    return v > 0.f ? v : e;
}

// packed fp32x2 helpers (sm_100+)
__device__ __forceinline__ void ffma2(unsigned long long& d, unsigned long long a, unsigned long long b) {
    asm("fma.rn.f32x2 %0, %1, %2, %0;" : "+l"(d) : "l"(a), "l"(b));
}
__device__ __forceinline__ float usum(unsigned long long v) {
    float lo, hi;
    asm("mov.b64 {%0,%1}, %2;" : "=f"(lo), "=f"(hi) : "l"(v));
    return lo + hi;
}
__device__ __forceinline__ void red_add_v4(float* addr, float x, float y, float z, float w) {
    asm volatile("red.global.add.v4.f32 [%0], {%1, %2, %3, %4};"
                 :: "l"(addr), "f"(x), "f"(y), "f"(z), "f"(w) : "memory");
}

// ------------------------------------------------------------------ launch 0: probe dtype + zero deg + prep fold (blocks 0,1)
__global__ void init_kernel(const int* __restrict__ w, int Nn,
                            const float* __restrict__ eW1, const float* __restrict__ eb1,
                            const float* __restrict__ nW0) {
    __shared__ float sE1[4096];
    __shared__ float sW0a[4096];
    __shared__ float sB1[64];

    if (blockIdx.x == 0 && threadIdx.x == 0) {
        bool all_odd_zero = true;
        for (int i = 1; i < 64; i += 2)
            if (w[i] != 0) { all_odd_zero = false; break; }
        g_mode = all_odd_zero ? 1 : 0;
    }
    // all blocks: zero deg
    for (int i = blockIdx.x * blockDim.x + threadIdx.x; i < Nn; i += gridDim.x * blockDim.x)
        g_deg[i] = 0;

    // blocks 0,1: fold eW1/eb1 into node W0 for layer l = blockIdx.x
    if (blockIdx.x < 2) {
        int l = blockIdx.x;
        const float* E1 = eW1 + (size_t)l * 4096;
        const float* B1 = eb1 + (size_t)l * 64;
        const float* W0 = nW0 + (size_t)l * 8192;
        for (int t = threadIdx.x; t < 4096; t += blockDim.x) {
            sE1[t]  = E1[t];
            sW0a[t] = W0[4096 + t];
        }
        if (threadIdx.x < 64) sB1[threadIdx.x] = B1[threadIdx.x];
        __syncthreads();

        if (threadIdx.x < 64) {
            float acc = 0.f;
            for (int m = 0; m < 64; m++) acc += sB1[m] * sW0a[m * 64 + threadIdx.x];
            g_v[l][threadIdx.x] = acc;
        }
        for (int t = threadIdx.x; t < 8192; t += blockDim.x) {
            int c = t & 3, lane_ = (t >> 2) & 31, kp = t >> 7;
            int k = 2 * kp + (c & 1);
            int col = lane_ + ((c & 2) ? 32 : 0);
            float val;
            if (k < 64) {
                val = W0[k * 64 + col];
            } else {
                int kk = k - 64;
                float acc = 0.f;
                for (int m = 0; m < 64; m++) acc += sE1[kk * 64 + m] * sW0a[m * 64 + col];
                val = acc;
            }
            g_W0c[l][t] = val;
        }
    }
}

// ------------------------------------------------------------------ launch 1: convert indices + deg + zero agg (layer 0)
__global__ void convert_kernel(const int* __restrict__ w, int Ecnt, int Nn) {
    int mode = g_mode;
    for (int e = blockIdx.x * blockDim.x + threadIdx.x; e < Ecnt; e += gridDim.x * blockDim.x) {
        int s, d;
        if (mode) { s = w[2 * e]; d = w[2 * (Ecnt + e)]; }
        else      { s = w[e];     d = w[Ecnt + e]; }
        s = min(max(s, 0), NNODE - 1);
        d = min(max(d, 0), NNODE - 1);
        atomicAdd(&g_deg[d], 1);
        g_sd[e] = make_int2(s * 128, d * 128);
    }
    float4* p = reinterpret_cast<float4*>(g_agg);
    int n4 = Nn * 16;
    for (int i = blockIdx.x * blockDim.x + threadIdx.x; i < n4; i += gridDim.x * blockDim.x)
        p[i] = make_float4(0.f, 0.f, 0.f, 0.f);
}

// ------------------------------------------------------------------ launch 2: encoder + precompute(layer 0) fused (batch 4)
__global__ void enc_pre_kernel(const float* __restrict__ x, const float* __restrict__ pos,
                               const float* __restrict__ W0e, const float* __restrict__ b0e,
                               const float* __restrict__ W1e, const float* __restrict__ b1e,
                               const float* __restrict__ E0, const float* __restrict__ eb0,
                               int Nn) {
    extern __shared__ float sm[];
    float* sW1 = sm;             // 4096 kpair-packed (enc W1)
    float* sWA = sm + 4096;      // 4096
    float* sWB = sm + 8192;      // 4096
    float* sW0 = sm + 12288;     // 192 (enc W0)
    float* sWp = sm + 12480;     // 192
    float* sbe0 = sm + 12672;    // 64
    float* sbe1 = sm + 12736;    // 64
    float* sb0  = sm + 12800;    // 64 (edge b0)
    float* stage = sm + 12864;   // 8 warps * 320

    for (int t = threadIdx.x; t < 4096; t += blockDim.x) {
        int c = t & 3, lane_ = (t >> 2) & 31, kp = t >> 7;
        int k = 2 * kp + (c & 1);
        int col = lane_ + ((c & 2) ? 32 : 0);
        sW1[t] = W1e[k * 64 + col];
        float wC = E0[(128 + k) * 64 + col];
        sWA[t] = E0[k * 64 + col] + wC;
        sWB[t] = E0[(64 + k) * 64 + col] - wC;
    }
    for (int t = threadIdx.x; t < 192; t += blockDim.x) {
        sW0[t] = W0e[t];
        sWp[t] = E0[(192 + (t >> 6)) * 64 + (t & 63)];
    }
    if (threadIdx.x < 64) {
        sbe0[threadIdx.x] = b0e[threadIdx.x];
        sbe1[threadIdx.x] = b1e[threadIdx.x];
        sb0[threadIdx.x]  = eb0[threadIdx.x];
    }
    __syncthreads();

    int lane = threadIdx.x & 31;
    int wid  = threadIdx.x >> 5;
    float* wbase = stage + wid * 320;
    const ulonglong2* W1v = reinterpret_cast<const ulonglong2*>(sW1);
    const ulonglong2* WAv = reinterpret_cast<const ulonglong2*>(sWA);
    const ulonglong2* WBv = reinterpret_cast<const ulonglong2*>(sWB);
    const unsigned long long* nU = reinterpret_cast<const unsigned long long*>(wbase);
    float* hF = wbase;

    int rL = ((lane >> 1) * 5) * 2 + (lane & 1);
    int rH = ((16 + (lane >> 1)) * 5) * 2 + (lane & 1);

    int wg = blockIdx.x * (blockDim.x >> 5) + wid;
    int ws = gridDim.x * (blockDim.x >> 5);
    for (int base = wg * 4; base < Nn; base += ws * 4) {
        float p0v[4], p1v[4], p2v[4];
#pragma unroll
        for (int i = 0; i < 4; i++) {
            int n = base + i;
            float h0 = 0.f, h1 = 0.f;
            if (n < Nn) {
                float x0 = __ldg(&x[n * 3 + 0]), x1 = __ldg(&x[n * 3 + 1]), x2 = __ldg(&x[n * 3 + 2]);
                h0 = elu_f(x0 * sW0[lane]      + x1 * sW0[64 + lane]      + x2 * sW0[128 + lane]      + sbe0[lane]);
                h1 = elu_f(x0 * sW0[lane + 32] + x1 * sW0[64 + lane + 32] + x2 * sW0[128 + lane + 32] + sbe0[lane + 32]);
                p0v[i] = __ldg(&pos[n * 3 + 0]);
                p1v[i] = __ldg(&pos[n * 3 + 1]);
                p2v[i] = __ldg(&pos[n * 3 + 2]);
            } else { p0v[i] = p1v[i] = p2v[i] = 0.f; }
            hF[rL + 2 * i] = h0;
            hF[rH + 2 * i] = h1;
        }
        __syncwarp();

        unsigned long long a0[4] = {0,0,0,0}, a1[4] = {0,0,0,0};
#pragma unroll 4
        for (int kp = 0; kp < 32; kp++) {
            ulonglong2 w = W1v[kp * 32 + lane];
#pragma unroll
            for (int i = 0; i < 4; i++) {
                unsigned long long v = nU[kp * 5 + i];
                ffma2(a0[i], v, w.x); ffma2(a1[i], v, w.y);
            }
        }
        float b1a = sbe1[lane], b1b = sbe1[lane + 32];
        float hL[4], hH[4];
#pragma unroll
        for (int i = 0; i < 4; i++) {
            hL[i] = usum(a0[i]) + b1a;
            hH[i] = usum(a1[i]) + b1b;
            int n = base + i;
            if (n < Nn) {
                g_h[n * 64 + lane]      = hL[i];
                g_h[n * 64 + 32 + lane] = hH[i];
            }
        }
        __syncwarp();
#pragma unroll
        for (int i = 0; i < 4; i++) {
            hF[rL + 2 * i] = hL[i];
            hF[rH + 2 * i] = hH[i];
        }
        __syncwarp();

        unsigned long long aA0[4] = {0,0,0,0}, aA1[4] = {0,0,0,0};
        unsigned long long aB0[4] = {0,0,0,0}, aB1[4] = {0,0,0,0};
#pragma unroll 4
        for (int kp = 0; kp < 32; kp++) {
            ulonglong2 wa = WAv[kp * 32 + lane];
            ulonglong2 wb = WBv[kp * 32 + lane];
#pragma unroll
            for (int i = 0; i < 4; i++) {
                unsigned long long v = nU[kp * 5 + i];
                ffma2(aA0[i], v, wa.x); ffma2(aA1[i], v, wa.y);
                ffma2(aB0[i], v, wb.x); ffma2(aB1[i], v, wb.y);
            }
        }
        float b0a = sb0[lane], b0b = sb0[lane + 32];
        float wpL0 = sWp[lane], wpL1 = sWp[64 + lane], wpL2 = sWp[128 + lane];
        float wpH0 = sWp[lane + 32], wpH1 = sWp[64 + lane + 32], wpH2 = sWp[128 + lane + 32];
#pragma unroll
        for (int i = 0; i < 4; i++) {
            int n = base + i;
            if (n < Nn) {
                float wpa = p0v[i] * wpL0 + p1v[i] * wpL1 + p2v[i] * wpL2;
                float wpb = p0v[i] * wpH0 + p1v[i] * wpH1 + p2v[i] * wpH2;
                g_PAh[n * 64 + lane]      = __float2half(usum(aA0[i]) + wpa);
                g_PAh[n * 64 + 32 + lane] = __float2half(usum(aA1[i]) + wpb);
                g_PBh[n * 64 + lane]      = __float2half(usum(aB0[i]) + b0a - wpa);
                g_PBh[n * 64 + 32 + lane] = __float2half(usum(aB1[i]) + b0b - wpb);
            }
        }
        __syncwarp();
    }
}

// ------------------------------------------------------------------ launch 3 (PROFILED): edge scatter (fp16 gathers) — round-12 proven
__global__ void edge_scatter_kernel(int Ecnt) {
    int lane = threadIdx.x & 31;
    int wid  = threadIdx.x >> 5;
    int slot = lane >> 4;
    int ch8  = (lane & 15) * 8;

    const char* PAc = reinterpret_cast<const char*>(g_PAh) + ch8;
    const char* PBc = reinterpret_cast<const char*>(g_PBh) + ch8;
    char*       AGc = reinterpret_cast<char*>(g_agg) + ch8 * 2;

    int wg = blockIdx.x * (blockDim.x >> 5) + wid;
    int ws = gridDim.x * (blockDim.x >> 5);
    for (int base = wg * 8; base < Ecnt; base += ws * 8) {
        int2 ed[4];
        uint2 pa[4], pb[4];
#pragma unroll
        for (int p = 0; p < 4; p++) {
            int e = base + p * 2 + slot;
            ed[p] = (e < Ecnt) ? __ldg(&g_sd[e]) : make_int2(-1, -1);
        }
#pragma unroll
        for (int p = 0; p < 4; p++) {
            if (ed[p].x >= 0) {
                pa[p] = *reinterpret_cast<const uint2*>(PAc + ed[p].x);
                pb[p] = *reinterpret_cast<const uint2*>(PBc + ed[p].y);
            }
        }
#pragma unroll
        for (int p = 0; p < 4; p++) {
            if (ed[p].x >= 0) {
                float2 a0 = __half22float2(*reinterpret_cast<__half2*>(&pa[p].x));
                float2 a1 = __half22float2(*reinterpret_cast<__half2*>(&pa[p].y));
                float2 b0 = __half22float2(*reinterpret_cast<__half2*>(&pb[p].x));
                float2 b1 = __half22float2(*reinterpret_cast<__half2*>(&pb[p].y));
                float hx = elu_fast(a0.x + b0.x);
                float hy = elu_fast(a0.y + b0.y);
                float hz = elu_fast(a1.x + b1.x);
                float hw = elu_fast(a1.y + b1.y);
                red_add_v4(reinterpret_cast<float*>(AGc + ((size_t)ed[p].y << 1)), hx, hy, hz, hw);
            }
        }
    }
}

// ------------------------------------------------------------------ node_pre: node update (l0) + precompute(l1) + zero agg  (BATCH 6)
__global__ void node_pre_kernel(const float* __restrict__ W0c, const float* __restrict__ vv,
                                const float* __restrict__ W1, const float* __restrict__ b0,
                                const float* __restrict__ b1,
                                const float* __restrict__ E0, const float* __restrict__ eb0_1,
                                const float* __restrict__ pos, int Nn) {
    extern __shared__ float sm[];
    float* sW0 = sm;              // 8192
    float* sW1 = sm + 8192;       // 4096
    float* sWA = sm + 12288;      // 4096 (layer 1)
    float* sWB = sm + 16384;      // 4096
    float* sWp = sm + 20480;      // 192
    float* sv  = sm + 20672;      // 64
    float* snb0 = sm + 20736;     // 64
    float* snb1 = sm + 20800;     // 64
    float* seb0 = sm + 20864;     // 64
    float* stage = sm + 20928;    // 8 warps * 896 floats (64 kpairs * 7 u64)

    for (int t = threadIdx.x; t < 8192; t += blockDim.x) sW0[t] = W0c[t];
    for (int t = threadIdx.x; t < 4096; t += blockDim.x) {
        int c = t & 3, lane_ = (t >> 2) & 31, kp = t >> 7;
        int k = 2 * kp + (c & 1);
        int col = lane_ + ((c & 2) ? 32 : 0);
        sW1[t] = W1[k * 64 + col];
        float wC = E0[(128 + k) * 64 + col];
        sWA[t] = E0[k * 64 + col] + wC;
        sWB[t] = E0[(64 + k) * 64 + col] - wC;
    }
    for (int t = threadIdx.x; t < 192; t += blockDim.x)
        sWp[t] = E0[(192 + (t >> 6)) * 64 + (t & 63)];
    if (threadIdx.x < 64) {
        sv[threadIdx.x]   = vv[threadIdx.x];
        snb0[threadIdx.x] = b0[threadIdx.x];
        snb1[threadIdx.x] = b1[threadIdx.x];
        seb0[threadIdx.x] = eb0_1[threadIdx.x];
    }
    __syncthreads();

    int lane = threadIdx.x & 31;
    int wid  = threadIdx.x >> 5;
    float* wbase = stage + wid * 896;
    float2* nP = reinterpret_cast<float2*>(wbase);   // u64-indexed, stride 7 per kpair
    const ulonglong2* W0v = reinterpret_cast<const ulonglong2*>(sW0);
    const ulonglong2* W1v = reinterpret_cast<const ulonglong2*>(sW1);
    const ulonglong2* WAv = reinterpret_cast<const ulonglong2*>(sWA);
    const ulonglong2* WBv = reinterpret_cast<const ulonglong2*>(sWB);
    const unsigned long long* nU = reinterpret_cast<const unsigned long long*>(nP);
    float* hF = wbase;

    int rL = ((lane >> 1) * 7) * 2 + (lane & 1);
    int rH = ((16 + (lane >> 1)) * 7) * 2 + (lane & 1);
    float wpL0 = sWp[lane], wpL1 = sWp[64 + lane], wpL2 = sWp[128 + lane];
    float wpH0 = sWp[lane + 32], wpH1 = sWp[64 + lane + 32], wpH2 = sWp[128 + lane + 32];

    int wg = blockIdx.x * (blockDim.x >> 5) + wid;
    int ws = gridDim.x * (blockDim.x >> 5);
    for (int base = wg * 6; base < Nn; base += ws * 6) {
        float degf[6], wpa[6], wpb[6];
#pragma unroll
        for (int i = 0; i < 6; i++) {
            int n = base + i;
            if (n < Nn) {
                nP[lane * 7 + i]        = reinterpret_cast<const float2*>(g_h + n * 64)[lane];
                nP[(32 + lane) * 7 + i] = reinterpret_cast<const float2*>(g_agg + n * 64)[lane];
                degf[i] = (float)__ldg(&g_deg[n]);
                float q0 = __ldg(&pos[n * 3 + 0]);
                float q1 = __ldg(&pos[n * 3 + 1]);
                float q2 = __ldg(&pos[n * 3 + 2]);
                wpa[i] = q0 * wpL0 + q1 * wpL1 + q2 * wpL2;
                wpb[i] = q0 * wpH0 + q1 * wpH1 + q2 * wpH2;
                reinterpret_cast<float2*>(g_agg + n * 64)[lane] = make_float2(0.f, 0.f);
            } else {
                nP[lane * 7 + i]        = make_float2(0.f, 0.f);
                nP[(32 + lane) * 7 + i] = make_float2(0.f, 0.f);
                degf[i] = 0.f; wpa[i] = 0.f; wpb[i] = 0.f;
            }
        }
        __syncwarp();

        // hidden = elu([h, Hsum]·W0c + deg·v + b0)
        unsigned long long c0[6] = {0,0,0,0,0,0}, c1[6] = {0,0,0,0,0,0};
#pragma unroll 4
        for (int kp = 0; kp < 64; kp++) {
            ulonglong2 w = W0v[kp * 32 + lane];
#pragma unroll
            for (int i = 0; i < 6; i++) {
                unsigned long long v = nU[kp * 7 + i];
                ffma2(c0[i], v, w.x); ffma2(c1[i], v, w.y);
            }
        }
        {
            float b0a = snb0[lane], b0b = snb0[lane + 32];
            float svL = sv[lane],   svH = sv[lane + 32];
            float hL[6], hH[6];
#pragma unroll
            for (int i = 0; i < 6; i++) {
                hL[i] = elu_f(usum(c0[i]) + degf[i] * svL + b0a);
                hH[i] = elu_f(usum(c1[i]) + degf[i] * svH + b0b);
            }
            __syncwarp();
#pragma unroll
            for (int i = 0; i < 6; i++) {
                hF[rL + 2 * i] = hL[i];
                hF[rH + 2 * i] = hH[i];
            }
        }
        __syncwarp();

        // u = hidden·W1 + b1 ; newh = oldh + u → g_h and restage
#pragma unroll
        for (int i = 0; i < 6; i++) { c0[i] = 0ull; c1[i] = 0ull; }
#pragma unroll 4
        for (int kp = 0; kp < 32; kp++) {
            ulonglong2 w = W1v[kp * 32 + lane];
#pragma unroll
            for (int i = 0; i < 6; i++) {
                unsigned long long v = nU[kp * 7 + i];
                ffma2(c0[i], v, w.x); ffma2(c1[i], v, w.y);
            }
        }
        {
            float b1a = snb1[lane], b1b = snb1[lane + 32];
            float nhL[6], nhH[6];
#pragma unroll
            for (int i = 0; i < 6; i++) {
                int n = base + i;
                if (n < Nn) {
                    nhL[i] = g_h[n * 64 + lane]      + usum(c0[i]) + b1a;
                    nhH[i] = g_h[n * 64 + 32 + lane] + usum(c1[i]) + b1b;
                    g_h[n * 64 + lane]      = nhL[i];
                    g_h[n * 64 + 32 + lane] = nhH[i];
                } else { nhL[i] = 0.f; nhH[i] = 0.f; }
            }
            __syncwarp();
#pragma unroll
            for (int i = 0; i < 6; i++) {
                hF[rL + 2 * i] = nhL[i];
                hF[rH + 2 * i] = nhH[i];
            }
        }
        __syncwarp();

        // PA pass (layer 1)
#pragma unroll
        for (int i = 0; i < 6; i++) { c0[i] = 0ull; c1[i] = 0ull; }
#pragma unroll 4
        for (int kp = 0; kp < 32; kp++) {
            ulonglong2 wa = WAv[kp * 32 + lane];
#pragma unroll
            for (int i = 0; i < 6; i++) {
                unsigned long long v = nU[kp * 7 + i];
                ffma2(c0[i], v, wa.x); ffma2(c1[i], v, wa.y);
            }
        }
#pragma unroll
        for (int i = 0; i < 6; i++) {
            int n = base + i;
            if (n < Nn) {
                g_PAh[n * 64 + lane]      = __float2half(usum(c0[i]) + wpa[i]);
                g_PAh[n * 64 + 32 + lane] = __float2half(usum(c1[i]) + wpb[i]);
            }
        }

        // PB pass (layer 1)
#pragma unroll
        for (int i = 0; i < 6; i++) { c0[i] = 0ull; c1[i] = 0ull; }
#pragma unroll 4
        for (int kp = 0; kp < 32; kp++) {
            ulonglong2 wb = WBv[kp * 32 + lane];
#pragma unroll
            for (int i = 0; i < 6; i++) {
                unsigned long long v = nU[kp * 7 + i];
                ffma2(c0[i], v, wb.x); ffma2(c1[i], v, wb.y);
            }
        }
        {
            float eb0a = seb0[lane], eb0b = seb0[lane + 32];
#pragma unroll
            for (int i = 0; i < 6; i++) {
                int n = base + i;
                if (n < Nn) {
                    g_PBh[n * 64 + lane]      = __float2half(usum(c0[i]) + eb0a - wpa[i]);
                    g_PBh[n * 64 + 32 + lane] = __float2half(usum(c1[i]) + eb0b - wpb[i]);
                }
            }
        }
        __syncwarp();
    }
}

// ------------------------------------------------------------------ node_dec: node update (l1) + decoder  (BATCH 6)
__global__ void node_dec_kernel(const float* __restrict__ W0c, const float* __restrict__ vv,
                                const float* __restrict__ W1, const float* __restrict__ b0,
                                const float* __restrict__ b1,
                                const float* __restrict__ dW0, const float* __restrict__ db0,
                                const float* __restrict__ dW1, const float* __restrict__ db1,
                                float* __restrict__ out, int Nn) {
    extern __shared__ float sm[];
    float* sW0 = sm;              // 8192
    float* sW1 = sm + 8192;       // 4096
    float* sdW0 = sm + 12288;     // 4096
    float* sdW1 = sm + 16384;     // 192
    float* sv  = sm + 16576;      // 64
    float* snb0 = sm + 16640;     // 64
    float* snb1 = sm + 16704;     // 64
    float* sdb0 = sm + 16768;     // 64
    float* sdb1 = sm + 16832;     // 4
    float* stage = sm + 16836;    // 8 warps * 896

    for (int t = threadIdx.x; t < 8192; t += blockDim.x) sW0[t] = W0c[t];
    for (int t = threadIdx.x; t < 4096; t += blockDim.x) {
        int c = t & 3, lane_ = (t >> 2) & 31, kp = t >> 7;
        int k = 2 * kp + (c & 1);
        int col = lane_ + ((c & 2) ? 32 : 0);
        sW1[t] = W1[k * 64 + col];
        sdW0[t] = dW0[k * 64 + col];
    }
    for (int t = threadIdx.x; t < 192; t += blockDim.x) sdW1[t] = dW1[t];
    if (threadIdx.x < 64) {
        sv[threadIdx.x]   = vv[threadIdx.x];
        snb0[threadIdx.x] = b0[threadIdx.x];
        snb1[threadIdx.x] = b1[threadIdx.x];
        sdb0[threadIdx.x] = db0[threadIdx.x];
    }
    if (threadIdx.x < 3) sdb1[threadIdx.x] = db1[threadIdx.x];
    __syncthreads();

    int lane = threadIdx.x & 31;
    int wid  = threadIdx.x >> 5;
    float* wbase = stage + wid * 896;
    float2* nP = reinterpret_cast<float2*>(wbase);
    const ulonglong2* W0v = reinterpret_cast<const ulonglong2*>(sW0);
    const ulonglong2* W1v = reinterpret_cast<const ulonglong2*>(sW1);
    const ulonglong2* dW0v = reinterpret_cast<const ulonglong2*>(sdW0);
    const unsigned long long* nU = reinterpret_cast<const unsigned long long*>(nP);
    float* hF = wbase;

    int rL = ((lane >> 1) * 7) * 2 + (lane & 1);
    int rH = ((16 + (lane >> 1)) * 7) * 2 + (lane & 1);

    int wg = blockIdx.x * (blockDim.x >> 5) + wid;
    int ws = gridDim.x * (blockDim.x >> 5);
    for (int base = wg * 6; base < Nn; base += ws * 6) {
        float degf[6];
#pragma unroll
        for (int i = 0; i < 6; i++) {
            int n = base + i;
            if (n < Nn) {
                nP[lane * 7 + i]        = reinterpret_cast<const float2*>(g_h + n * 64)[lane];
                nP[(32 + lane) * 7 + i] = reinterpret_cast<const float2*>(g_agg + n * 64)[lane];
                degf[i] = (float)__ldg(&g_deg[n]);
            } else {
                nP[lane * 7 + i]        = make_float2(0.f, 0.f);
                nP[(32 + lane) * 7 + i] = make_float2(0.f, 0.f);
                degf[i] = 0.f;
            }
        }
        __syncwarp();

        // hidden = elu([h, Hsum]·W0c + deg·v + b0)
        unsigned long long c0[6] = {0,0,0,0,0,0}, c1[6] = {0,0,0,0,0,0};
#pragma unroll 4
        for (int kp = 0; kp < 64; kp++) {
            ulonglong2 w = W0v[kp * 32 + lane];
#pragma unroll
            for (int i = 0; i < 6; i++) {
                unsigned long long v = nU[kp * 7 + i];
                ffma2(c0[i], v, w.x); ffma2(c1[i], v, w.y);
            }
        }
        {
            float b0a = snb0[lane], b0b = snb0[lane + 32];
            float svL = sv[lane],   svH = sv[lane + 32];
            float hL[6], hH[6];
#pragma unroll
            for (int i = 0; i < 6; i++) {
                hL[i] = elu_f(usum(c0[i]) + degf[i] * svL + b0a);
                hH[i] = elu_f(usum(c1[i]) + degf[i] * svH + b0b);
            }
            __syncwarp();
#pragma unroll
            for (int i = 0; i < 6; i++) {
                hF[rL + 2 * i] = hL[i];
                hF[rH + 2 * i] = hH[i];
            }
        }
        __syncwarp();

        // u = hidden·W1 + b1 ; newh = oldh + u (registers → restage)
#pragma unroll
        for (int i = 0; i < 6; i++) { c0[i] = 0ull; c1[i] = 0ull; }
#pragma unroll 4
        for (int kp = 0; kp < 32; kp++) {
            ulonglong2 w = W1v[kp * 32 + lane];
#pragma unroll
            for (int i = 0; i < 6; i++) {
                unsigned long long v = nU[kp * 7 + i];
                ffma2(c0[i], v, w.x); ffma2(c1[i], v, w.y);
            }
        }
        {
            float b1a = snb1[lane], b1b = snb1[lane + 32];
            float nhL[6], nhH[6];
#pragma unroll
            for (int i = 0; i < 6; i++) {
                int n = base + i;
                if (n < Nn) {
                    nhL[i] = g_h[n * 64 + lane]      + usum(c0[i]) + b1a;
                    nhH[i] = g_h[n * 64 + 32 + lane] + usum(c1[i]) + b1b;
                } else { nhL[i] = 0.f; nhH[i] = 0.f; }
            }
            __syncwarp();
#pragma unroll
            for (int i = 0; i < 6; i++) {
                hF[rL + 2 * i] = nhL[i];
                hF[rH + 2 * i] = nhH[i];
            }
        }
        __syncwarp();

        // decoder: hidden = elu(newh·dW0 + db0) ; out = hidden·dW1 + db1
#pragma unroll
        for (int i = 0; i < 6; i++) { c0[i] = 0ull; c1[i] = 0ull; }
#pragma unroll 4
        for (int kp = 0; kp < 32; kp++) {
            ulonglong2 w = dW0v[kp * 32 + lane];
#pragma unroll
            for (int i = 0; i < 6; i++) {
                unsigned long long v = nU[kp * 7 + i];
                ffma2(c0[i], v, w.x); ffma2(c1[i], v, w.y);
            }
        }
        float db0a = sdb0[lane], db0b = sdb0[lane + 32];
        float w1L0 = sdW1[lane * 3 + 0], w1L1 = sdW1[lane * 3 + 1], w1L2 = sdW1[lane * 3 + 2];
        float w1H0 = sdW1[(lane + 32) * 3 + 0], w1H1 = sdW1[(lane + 32) * 3 + 1], w1H2 = sdW1[(lane + 32) * 3 + 2];
#pragma unroll
        for (int i = 0; i < 6; i++) {
            int n = base + i;
            float hid0 = elu_f(usum(c0[i]) + db0a);
            float hid1 = elu_f(usum(c1[i]) + db0b);
            float p0 = hid0 * w1L0 + hid1 * w1H0;
            float p1 = hid0 * w1L1 + hid1 * w1H1;
            float p2 = hid0 * w1L2 + hid1 * w1H2;
#pragma unroll
            for (int off = 16; off; off >>= 1) {
                p0 += __shfl_xor_sync(~0u, p0, off);
                p1 += __shfl_xor_sync(~0u, p1, off);
                p2 += __shfl_xor_sync(~0u, p2, off);
            }
            if (lane == 0 && n < Nn) {
                out[n * 3 + 0] = p0 + sdb1[0];
                out[n * 3 + 1] = p1 + sdb1[1];
                out[n * 3 + 2] = p2 + sdb1[2];
            }
        }
        __syncwarp();
    }
}

// ------------------------------------------------------------------ launch
extern "C" void kernel_launch(void* const* d_in, const int* in_sizes, int n_in,
                              void* d_out, int out_size) {
    const float* x      = (const float*)d_in[0];
    const float* pos    = (const float*)d_in[1];
    const int*   ei     = (const int*)d_in[2];
    const float* enc_W0 = (const float*)d_in[3];
    const float* enc_b0 = (const float*)d_in[4];
    const float* enc_W1 = (const float*)d_in[5];
    const float* enc_b1 = (const float*)d_in[6];
    const float* dec_W0 = (const float*)d_in[7];
    const float* dec_b0 = (const float*)d_in[8];
    const float* dec_W1 = (const float*)d_in[9];
    const float* dec_b1 = (const float*)d_in[10];
    const float* eW0    = (const float*)d_in[11];
    const float* eb0    = (const float*)d_in[12];
    const float* eW1    = (const float*)d_in[13];
    const float* eb1    = (const float*)d_in[14];
    const float* nW0    = (const float*)d_in[15];
    const float* nb0    = (const float*)d_in[16];
    const float* nW1    = (const float*)d_in[17];
    const float* nb1    = (const float*)d_in[18];

    int Nn   = in_sizes[0] / 3;
    int Ecnt = in_sizes[2] / 2;
    if (Ecnt > EMAX) Ecnt = EMAX;
    float* out = (float*)d_out;

    const int ENCP_SMEM = (12864 + 8 * 320) * 4;   // 61,696 B
    const int NPRE_SMEM = (20928 + 8 * 896) * 4;   // 112,384 B  (2 blocks/SM)
    const int NDEC_SMEM = (16836 + 8 * 896) * 4;   // 96,016 B   (2 blocks/SM)
    cudaFuncSetAttribute(enc_pre_kernel,  cudaFuncAttributeMaxDynamicSharedMemorySize, ENCP_SMEM);
    cudaFuncSetAttribute(node_pre_kernel, cudaFuncAttributeMaxDynamicSharedMemorySize, NPRE_SMEM);
    cudaFuncSetAttribute(node_dec_kernel, cudaFuncAttributeMaxDynamicSharedMemorySize, NDEC_SMEM);

    const int TPB = 256;
    const float* E0_0 = eW0;
    const float* E0_1 = eW0 + (size_t)195 * 64;

    float* w0c; float* vv;
    cudaGetSymbolAddress((void**)&w0c, g_W0c);
    cudaGetSymbolAddress((void**)&vv,  g_v);

    init_kernel<<<148, TPB>>>(ei, Nn, eW1, eb1, nW0);                                 // 0 (probe+zero+prep)
    convert_kernel<<<444, TPB>>>(ei, Ecnt, Nn);                                       // 1
    enc_pre_kernel<<<296, TPB, ENCP_SMEM>>>(x, pos, enc_W0, enc_b0, enc_W1, enc_b1,
                                            E0_0, eb0, Nn);                           // 2
    edge_scatter_kernel<<<888, TPB>>>(Ecnt);                                          // 3  ← profiled
    node_pre_kernel<<<296, TPB, NPRE_SMEM>>>(w0c, vv, nW1, nb0, nb1,
                                             E0_1, eb0 + 64, pos, Nn);                // 4
    edge_scatter_kernel<<<888, TPB>>>(Ecnt);                                          // 5
    node_dec_kernel<<<296, TPB, NDEC_SMEM>>>(w0c + 8192, vv + 64,
                                             nW1 + (size_t)64 * 64, nb0 + 64, nb1 + 64,
                                             dec_W0, dec_b0, dec_W1, dec_b1, out, Nn); // 6
}